// round 12
// baseline (speedup 1.0000x reference)
#include <cuda_runtime.h>
#include <math.h>
#include <stdint.h>

// Problem constants
constexpr int T_SEQ  = 2048;
constexpr int NB     = 2;
constexpr int NH     = 4;
constexpr int DK     = 256;
constexpr int DV     = 512;
constexpr int DMODEL = 1024;
constexpr int KDIM   = NH * DK;    // 1024
constexpr int VDIM   = NH * DV;    // 2048
constexpr int MROWS  = NB * T_SEQ; // 4096
constexpr int CHK    = 128;
constexpr int NCH    = T_SEQ / CHK; // 16
constexpr int STSZ   = DV * DK;     // 131072

// Scratch (device globals; no allocations allowed)
__device__ __align__(128) float g_q[MROWS * KDIM];
__device__ __align__(128) float g_k[MROWS * KDIM];
__device__ __align__(128) float g_v[MROWS * VDIM];
__device__ __align__(128) float g_g[MROWS * VDIM];
__device__ __align__(128) float g_o[MROWS * VDIM];
__device__ __align__(128) float g_x[MROWS * DMODEL];         // rounded x
__device__ __align__(128) float g_w[8 * 1024 * 1024];        // rounded weights
__device__ __align__(128) float g_state[NB * NH * NCH * STSZ];

// weight offsets in g_w (floats)
constexpr long long WQ_OFF = 0;
constexpr long long WK_OFF = 1048576;
constexpr long long WV_OFF = 2097152;
constexpr long long WG_OFF = 4194304;
constexpr long long WO_OFF = 6291456;

__device__ __forceinline__ unsigned f2tf(float f) {
    unsigned u;
    asm("cvt.rna.tf32.f32 %0, %1;" : "=r"(u) : "f"(f));
    return u;
}
__device__ __forceinline__ float roundtf(float f) { return __uint_as_float(f2tf(f)); }

__device__ __forceinline__ void mma_tf32(float* c, const unsigned* a, const unsigned* b) {
    asm volatile(
        "mma.sync.aligned.m16n8k8.row.col.f32.tf32.tf32.f32 "
        "{%0,%1,%2,%3}, {%4,%5,%6,%7}, {%8,%9}, {%0,%1,%2,%3};\n"
        : "+f"(c[0]), "+f"(c[1]), "+f"(c[2]), "+f"(c[3])
        : "r"(a[0]), "r"(a[1]), "r"(a[2]), "r"(a[3]), "r"(b[0]), "r"(b[1]));
}

__device__ __forceinline__ void ldsm_x4(unsigned* r, uint32_t addr) {
    asm volatile("ldmatrix.sync.aligned.m8n8.x4.shared.b16 {%0,%1,%2,%3}, [%4];"
                 : "=r"(r[0]), "=r"(r[1]), "=r"(r[2]), "=r"(r[3]) : "r"(addr));
}

__device__ __forceinline__ float head_lam(int h) {
    return logf(1.0f - exp2f(-5.0f - (float)h));
}

__device__ __forceinline__ void cpasync16(unsigned dst, const void* src) {
    asm volatile("cp.async.cg.shared.global [%0], [%1], 16;\n" :: "r"(dst), "l"(src));
}
__device__ __forceinline__ void cp_commit() {
    asm volatile("cp.async.commit_group;\n" ::: "memory");
}
__device__ __forceinline__ void cp_wait1() {
    asm volatile("cp.async.wait_group 1;\n" ::: "memory");
}
__device__ __forceinline__ uint32_t smem_u32(const void* p) {
    uint32_t a;
    asm("{ .reg .u64 t; cvta.to.shared.u64 t, %1; cvt.u32.u64 %0, t; }" : "=r"(a) : "l"(p));
    return a;
}

// ---------------------------------------------------------------------------
// Fused rounding copy for all 6 inputs (one launch).
// Segment boundaries in float4 units.
// ---------------------------------------------------------------------------
__global__ __launch_bounds__(256) void round_all(
    const float* __restrict__ x,  const float* __restrict__ wq,
    const float* __restrict__ wk, const float* __restrict__ wv,
    const float* __restrict__ wg, const float* __restrict__ wo)
{
    int i = blockIdx.x * 256 + threadIdx.x;
    const float* src; float* dst; int off;
    if      (i < 1048576) { src = x;  dst = g_x;          off = i; }
    else if (i < 1310720) { src = wq; dst = g_w + WQ_OFF; off = i - 1048576; }
    else if (i < 1572864) { src = wk; dst = g_w + WK_OFF; off = i - 1310720; }
    else if (i < 2097152) { src = wv; dst = g_w + WV_OFF; off = i - 1572864; }
    else if (i < 2621440) { src = wg; dst = g_w + WG_OFF; off = i - 2097152; }
    else                  { src = wo; dst = g_w + WO_OFF; off = i - 2621440; }
    float4 v = ((const float4*)src)[off];
    ((float4*)dst)[off] = make_float4(roundtf(v.x), roundtf(v.y),
                                      roundtf(v.z), roundtf(v.w));
}

// ---------------------------------------------------------------------------
// TF32 GEMM, ldmatrix fragments, 3-stage cp.async, ONE sync per k-chunk.
// CTA tile 128x128, BK=32, 8 warps (4m x 2n), warp 32x64.
// Smem: row-major 128B rows, XOR-swizzled 16B granules (g ^= row&7).
// ---------------------------------------------------------------------------
constexpr int AT_B   = 128 * 128;           // 16 KB tile
constexpr int STG_B  = 2 * AT_B;            // 32 KB per stage
constexpr int GEMM_SMEM = 3 * STG_B;        // 98304 bytes

__device__ __forceinline__ void gemm_pipe(
    const float* __restrict__ Ab, const float* __restrict__ Wb,
    float* __restrict__ Cb, int ldc, int K, int roundC, char* smem)
{
    const int tid  = threadIdx.x;
    const int lane = tid & 31;
    const int wid  = tid >> 5;
    const int wm = (wid & 3) * 32;
    const int wn = (wid >> 2) * 64;
    const int gq = lane >> 2;
    const int tq = lane & 3;
    const int nk = K >> 5;
    const uint32_t sa = smem_u32(smem);

    const int a_row  = (lane & 7) + ((lane >> 3) & 1) * 8;
    const int a_gsel = lane >> 4;
    const int b_row  = (lane & 7) + (lane >> 4) * 8;
    const int b_gsel = (lane >> 3) & 1;

    float acc[2][8][4];
#pragma unroll
    for (int mt = 0; mt < 2; mt++)
#pragma unroll
        for (int nt = 0; nt < 8; nt++)
#pragma unroll
            for (int e = 0; e < 4; e++) acc[mt][nt][e] = 0.0f;

    auto cp_chunk = [&](int c) {
        uint32_t ab = sa + (c % 3) * STG_B;
        uint32_t bb = ab + AT_B;
        const float* Ap = Ab + c * 32;
        const float* Bp = Wb + c * 32;
#pragma unroll
        for (int i = 0; i < 4; i++) {
            int id = i * 256 + tid;
            int row = id >> 3, g = id & 7;
            cpasync16(ab + row * 128 + ((g ^ (row & 7)) << 4),
                      Ap + (size_t)row * K + g * 4);
        }
#pragma unroll
        for (int i = 0; i < 4; i++) {
            int id = i * 256 + tid;
            int row = id >> 3, g = id & 7;
            cpasync16(bb + row * 128 + ((g ^ (row & 7)) << 4),
                      Bp + (size_t)row * K + g * 4);
        }
        cp_commit();
    };

    cp_chunk(0); cp_chunk(1);

    for (int j = 0; j < nk; j++) {
        cp_wait1();
        __syncthreads();
        if (j + 2 < nk) cp_chunk(j + 2); else cp_commit();

        uint32_t ab = sa + (j % 3) * STG_B;
        uint32_t bb = ab + AT_B;
#pragma unroll
        for (int k8 = 0; k8 < 4; k8++) {
            const int gA = k8 * 2 + a_gsel;
            const int gB = k8 * 2 + b_gsel;
            unsigned af[2][4];
#pragma unroll
            for (int mt = 0; mt < 2; mt++) {
                int r = wm + mt * 16 + a_row;
                ldsm_x4(af[mt], ab + r * 128 + ((gA ^ (r & 7)) << 4));
            }
            unsigned bfr[4][4];
#pragma unroll
            for (int ntp = 0; ntp < 4; ntp++) {
                int r = wn + ntp * 16 + b_row;
                ldsm_x4(bfr[ntp], bb + r * 128 + ((gB ^ (r & 7)) << 4));
            }
#pragma unroll
            for (int ntp = 0; ntp < 4; ntp++) {
#pragma unroll
                for (int half = 0; half < 2; half++) {
                    unsigned bf[2] = { bfr[ntp][half * 2], bfr[ntp][half * 2 + 1] };
#pragma unroll
                    for (int mt = 0; mt < 2; mt++)
                        mma_tf32(acc[mt][ntp * 2 + half], af[mt], bf);
                }
            }
        }
    }

#pragma unroll
    for (int mt = 0; mt < 2; mt++) {
        int r0 = wm + mt * 16 + gq;
#pragma unroll
        for (int nt = 0; nt < 8; nt++) {
            int cc = wn + nt * 8 + tq * 2;
            float2 v0 = make_float2(acc[mt][nt][0], acc[mt][nt][1]);
            float2 v1 = make_float2(acc[mt][nt][2], acc[mt][nt][3]);
            if (roundC) {
                v0.x = roundtf(v0.x); v0.y = roundtf(v0.y);
                v1.x = roundtf(v1.x); v1.y = roundtf(v1.y);
            }
            *(float2*)(Cb + (size_t)r0 * ldc + cc)       = v0;
            *(float2*)(Cb + (size_t)(r0 + 8) * ldc + cc) = v1;
        }
    }
}

// Fused projections: x @ {Wq,Wk,Wv,Wg}^T. grid (48, 32).
__global__ __launch_bounds__(256, 2) void proj_gemm()
{
    extern __shared__ char smem[];
    const int bnx = blockIdx.x;
    const int bm  = blockIdx.y * 128;

    const float* Wb; float* Cc; int ldc, col, roundC = 0;
    if (bnx < 8)       { Wb = g_w + WQ_OFF; Cc = g_q; ldc = 1024; col = bnx * 128; }
    else if (bnx < 16) { Wb = g_w + WK_OFF; Cc = g_k; ldc = 1024; col = (bnx - 8) * 128; }
    else if (bnx < 32) { Wb = g_w + WV_OFF; Cc = g_v; ldc = 2048; col = (bnx - 16) * 128; roundC = 1; }
    else               { Wb = g_w + WG_OFF; Cc = g_g; ldc = 2048; col = (bnx - 32) * 128; }

    gemm_pipe(g_x + (size_t)bm * DMODEL, Wb + (size_t)col * DMODEL,
              Cc + (size_t)bm * ldc + col, ldc, DMODEL, roundC, smem);
}

// Output projection: (g_o rounded) @ Wo^T -> out. grid (8, 32).
__global__ __launch_bounds__(256, 2) void out_gemm(float* __restrict__ out)
{
    extern __shared__ char smem[];
    const int bn = blockIdx.x * 128;
    const int bm = blockIdx.y * 128;
    gemm_pipe(g_o + (size_t)bm * VDIM, g_w + WO_OFF + (size_t)bn * VDIM,
              out + (size_t)bm * DMODEL + bn, DMODEL, VDIM, 0, smem);
}

// ---------------------------------------------------------------------------
// RoPE (in place on g_q, g_k) + q scale by dk^-0.5 (fp32 path as reference).
// ---------------------------------------------------------------------------
__global__ __launch_bounds__(256) void rope_kernel()
{
    int idx = blockIdx.x * 256 + threadIdx.x;
    int i  = idx & 127;
    int h  = (idx >> 7) & 3;
    int bt = idx >> 9;
    int t  = bt & (T_SEQ - 1);
    size_t base = (size_t)bt * KDIM + h * DK;

    float e    = (float)(2 * i) * (1.0f / 256.0f);
    float invf = 1.0f / powf(10000.0f, e);
    float ang  = (float)t * invf;
    float sn, cs;
    sincosf(ang, &sn, &cs);

    float q1 = g_q[base + i], q2 = g_q[base + 128 + i];
    g_q[base + i]       = (q1 * cs - q2 * sn) * 0.0625f;
    g_q[base + 128 + i] = (q1 * sn + q2 * cs) * 0.0625f;
    float k1 = g_k[base + i], k2 = g_k[base + 128 + i];
    g_k[base + i]       = k1 * cs - k2 * sn;
    g_k[base + 128 + i] = k1 * sn + k2 * cs;
}

// ---------------------------------------------------------------------------
// Phase A: per (bh, chunk) U^T[dv, dk] = sum_i lam^(C-i) V[i,:]^T K[i,:]
// ldmatrix version: tiles stored as 256B rows (64 floats), swizzled.
// Vt [128 dv][64 i], Kt [128 dk][64 i]. 64 KB smem.
// ---------------------------------------------------------------------------
constexpr int KV_SMEM = 65536;

__global__ __launch_bounds__(256) void chunk_kv()
{
    extern __shared__ char smemk[];
    const uint32_t sb = smem_u32(smemk);
    const uint32_t Vt = sb;
    const uint32_t Kt = sb + 32768;

    const int tid  = threadIdx.x;
    const int lane = tid & 31;
    const int wid  = tid >> 5;
    const int gq = lane >> 2;
    const int tq = lane & 3;
    const int wm = (wid & 3) * 32;
    const int wn = (wid >> 2) * 64;

    const int a_row  = (lane & 7) + ((lane >> 3) & 1) * 8;
    const int a_gsel = lane >> 4;
    const int b_row  = (lane & 7) + (lane >> 4) * 8;
    const int b_gsel = (lane >> 3) & 1;

    const int dvt = blockIdx.x & 3;
    const int dkt = blockIdx.x >> 2;
    const int c   = blockIdx.y;
    const int bh  = blockIdx.z;
    const int b = bh >> 2, h = bh & 3;
    const float lam = head_lam(h);

    const int rowbase = b * T_SEQ + c * CHK;
    const float* Vb = g_v + (size_t)rowbase * VDIM + h * DV + dvt * 128;
    const float* Kb = g_k + (size_t)rowbase * KDIM + h * DK + dkt * 128;

    float acc[2][8][4];
#pragma unroll
    for (int mt = 0; mt < 2; mt++)
#pragma unroll
        for (int nt = 0; nt < 8; nt++)
#pragma unroll
            for (int e = 0; e < 4; e++) acc[mt][nt][e] = 0.0f;

    for (int sh = 0; sh < 2; sh++) {
        // transposed scatter: element (row, i) -> row*256 + swz granule
#pragma unroll
        for (int it = 0; it < 8; it++) {
            int id = it * 256 + tid;
            int n4 = id & 31;
            int i  = id >> 5;              // 0..63
            int gI = i >> 2, wI = (i & 3) * 4;
            float4 v = *(const float4*)(Vb + (size_t)(sh * 64 + i) * VDIM + n4 * 4);
            float w = expf(lam * (float)(CHK - (sh * 64 + i)));
            float4 kv = *(const float4*)(Kb + (size_t)(sh * 64 + i) * KDIM + n4 * 4);
            const float vv[4] = {v.x, v.y, v.z, v.w};
            const float kk4[4] = {kv.x * w, kv.y * w, kv.z * w, kv.w * w};
#pragma unroll
            for (int e = 0; e < 4; e++) {
                int row = n4 * 4 + e;
                uint32_t off = row * 256 + ((gI ^ (row & 7)) << 4) + wI;
                *(unsigned*)(smemk + off)         = f2tf(vv[e]);
                *(unsigned*)(smemk + 32768 + off) = f2tf(kk4[e]);
            }
        }
        __syncthreads();
#pragma unroll
        for (int k8 = 0; k8 < 8; k8++) {
            const int gA = k8 * 2 + a_gsel;
            const int gB = k8 * 2 + b_gsel;
            unsigned af[2][4];
#pragma unroll
            for (int mt = 0; mt < 2; mt++) {
                int r = wm + mt * 16 + a_row;
                ldsm_x4(af[mt], Vt + r * 256 + ((gA ^ (r & 7)) << 4));
            }
            unsigned bfr[4][4];
#pragma unroll
            for (int ntp = 0; ntp < 4; ntp++) {
                int r = wn + ntp * 16 + b_row;
                ldsm_x4(bfr[ntp], Kt + r * 256 + ((gB ^ (r & 7)) << 4));
            }
#pragma unroll
            for (int ntp = 0; ntp < 4; ntp++) {
#pragma unroll
                for (int half = 0; half < 2; half++) {
                    unsigned bf[2] = { bfr[ntp][half * 2], bfr[ntp][half * 2 + 1] };
#pragma unroll
                    for (int mt = 0; mt < 2; mt++)
                        mma_tf32(acc[mt][ntp * 2 + half], af[mt], bf);
                }
            }
        }
        __syncthreads();
    }

    float* St = g_state + (size_t)(bh * NCH + c) * STSZ;
#pragma unroll
    for (int mt = 0; mt < 2; mt++) {
        int r0 = dvt * 128 + wm + mt * 16 + gq;
#pragma unroll
        for (int nt = 0; nt < 8; nt++) {
            int cc = dkt * 128 + wn + nt * 8 + tq * 2;
            *(float2*)(St + (size_t)r0 * DK + cc)       = make_float2(acc[mt][nt][0], acc[mt][nt][1]);
            *(float2*)(St + (size_t)(r0 + 8) * DK + cc) = make_float2(acc[mt][nt][2], acc[mt][nt][3]);
        }
    }
}

// ---------------------------------------------------------------------------
// Phase B: prefix scan; stores tf32-rounded State snapshots (accum fp32).
// ---------------------------------------------------------------------------
__global__ __launch_bounds__(256) void state_scan()
{
    int tid4 = blockIdx.x * 256 + threadIdx.x;
    int bh   = tid4 >> 15;
    int off  = (tid4 & 32767) * 4;
    const float d = expf(head_lam(bh & 3) * (float)CHK);

    float* base = g_state + (size_t)bh * NCH * STSZ + off;
    float4 s = make_float4(0.f, 0.f, 0.f, 0.f);
#pragma unroll
    for (int c = 0; c < NCH; c++) {
        float4 u = *(float4*)(base + (size_t)c * STSZ);
        *(float4*)(base + (size_t)c * STSZ) =
            make_float4(roundtf(s.x), roundtf(s.y), roundtf(s.z), roundtf(s.w));
        s.x = d * s.x + u.x;
        s.y = d * s.y + u.y;
        s.z = d * s.z + u.z;
        s.w = d * s.w + u.w;
    }
}

// ---------------------------------------------------------------------------
// Phase C: O[128,128] = Qhat @ State^T + (mask . Q K^T) @ V, ldmatrix version.
// Smem: Qs 16KB (128x32f swz128) | Bs 16KB | Ss 32KB (128x64f swz256) | Vt 32KB
// ---------------------------------------------------------------------------
constexpr int CO_QS = 0;
constexpr int CO_BS = 16384;
constexpr int CO_SS = 32768;
constexpr int CO_VT = 65536;
constexpr int CO_SMEM = 98304;

__global__ __launch_bounds__(256) void chunk_out()
{
    extern __shared__ char smemc[];
    const uint32_t sb = smem_u32(smemc);
    const uint32_t Qs = sb + CO_QS;
    const uint32_t Bs = sb + CO_BS;
    const uint32_t Ss = sb + CO_SS;
    const uint32_t Vt = sb + CO_VT;

    const int tid  = threadIdx.x;
    const int lane = tid & 31;
    const int wid  = tid >> 5;
    const int gq = lane >> 2;
    const int tq = lane & 3;
    const int wm  = (wid & 3) * 32;
    const int wn  = (wid >> 2) * 64;
    const int wns = (wid >> 2) * 32;

    const int a_row  = (lane & 7) + ((lane >> 3) & 1) * 8;
    const int a_gsel = lane >> 4;
    const int b_row  = (lane & 7) + (lane >> 4) * 8;
    const int b_gsel = (lane >> 3) & 1;

    const int dvt = blockIdx.x;
    const int c   = blockIdx.y;
    const int bh  = blockIdx.z;
    const int b = bh >> 2, h = bh & 3;
    const float lam = head_lam(h);

    const int rowbase = b * T_SEQ + c * CHK;
    const float* Qb = g_q + (size_t)rowbase * KDIM + h * DK;
    const float* Kb = g_k + (size_t)rowbase * KDIM + h * DK;
    const float* Vb = g_v + (size_t)rowbase * VDIM + h * DV + dvt * 128;
    const float* St = g_state + (size_t)(bh * NCH + c) * STSZ + (size_t)dvt * 128 * DK;

    float oacc[2][8][4];
#pragma unroll
    for (int mt = 0; mt < 2; mt++)
#pragma unroll
        for (int nt = 0; nt < 8; nt++)
#pragma unroll
            for (int e = 0; e < 4; e++) oacc[mt][nt][e] = 0.0f;

    // ---------------- cross term: O += Qhat @ State^T ----------------
    for (int kc = 0; kc < DK; kc += 32) {
#pragma unroll
        for (int it = 0; it < 4; it++) {
            int id  = it * 256 + tid;
            int row = id >> 3;
            int g   = id & 7;
            uint32_t off = row * 128 + ((g ^ (row & 7)) << 4);
            float w = expf(lam * (float)row);
            float4 q = *(const float4*)(Qb + (size_t)row * KDIM + kc + g * 4);
            *(uint4*)(smemc + CO_QS + off) =
                make_uint4(f2tf(q.x * w), f2tf(q.y * w), f2tf(q.z * w), f2tf(q.w * w));
            float4 s = *(const float4*)(St + (size_t)row * DK + kc + g * 4);
            *(uint4*)(smemc + CO_BS + off) =
                make_uint4(f2tf(s.x), f2tf(s.y), f2tf(s.z), f2tf(s.w));
        }
        __syncthreads();
#pragma unroll
        for (int k8 = 0; k8 < 4; k8++) {
            const int gA = k8 * 2 + a_gsel;
            const int gB = k8 * 2 + b_gsel;
            unsigned af[2][4];
#pragma unroll
            for (int mt = 0; mt < 2; mt++) {
                int r = wm + mt * 16 + a_row;
                ldsm_x4(af[mt], Qs + r * 128 + ((gA ^ (r & 7)) << 4));
            }
            unsigned bfr[4][4];
#pragma unroll
            for (int ntp = 0; ntp < 4; ntp++) {
                int r = wn + ntp * 16 + b_row;
                ldsm_x4(bfr[ntp], Bs + r * 128 + ((gB ^ (r & 7)) << 4));
            }
#pragma unroll
            for (int ntp = 0; ntp < 4; ntp++) {
#pragma unroll
                for (int half = 0; half < 2; half++) {
                    unsigned bf[2] = { bfr[ntp][half * 2], bfr[ntp][half * 2 + 1] };
#pragma unroll
                    for (int mt = 0; mt < 2; mt++)
                        mma_tf32(oacc[mt][ntp * 2 + half], af[mt], bf);
                }
            }
        }
        __syncthreads();
    }

    // ---------------- intra term, two 64-key halves ----------------
    for (int sh = 0; sh < 2; sh++) {
        float sacc[2][4][4];
#pragma unroll
        for (int mt = 0; mt < 2; mt++)
#pragma unroll
            for (int nt = 0; nt < 4; nt++)
#pragma unroll
                for (int e = 0; e < 4; e++) sacc[mt][nt][e] = 0.0f;

        for (int kc = 0; kc < DK; kc += 32) {
#pragma unroll
            for (int it = 0; it < 4; it++) {
                int id  = it * 256 + tid;
                int row = id >> 3;
                int g   = id & 7;
                uint32_t off = row * 128 + ((g ^ (row & 7)) << 4);
                float4 q = *(const float4*)(Qb + (size_t)row * KDIM + kc + g * 4);
                *(uint4*)(smemc + CO_QS + off) =
                    make_uint4(f2tf(q.x), f2tf(q.y), f2tf(q.z), f2tf(q.w));
            }
#pragma unroll
            for (int it = 0; it < 2; it++) {
                int id  = it * 256 + tid;
                int row = id >> 3;             // 0..63
                int g   = id & 7;
                uint32_t off = row * 128 + ((g ^ (row & 7)) << 4);
                float4 kv = *(const float4*)(Kb + (size_t)(sh * 64 + row) * KDIM + kc + g * 4);
                *(uint4*)(smemc + CO_BS + off) =
                    make_uint4(f2tf(kv.x), f2tf(kv.y), f2tf(kv.z), f2tf(kv.w));
            }
            __syncthreads();
#pragma unroll
            for (int k8 = 0; k8 < 4; k8++) {
                const int gA = k8 * 2 + a_gsel;
                const int gB = k8 * 2 + b_gsel;
                unsigned af[2][4];
#pragma unroll
                for (int mt = 0; mt < 2; mt++) {
                    int r = wm + mt * 16 + a_row;
                    ldsm_x4(af[mt], Qs + r * 128 + ((gA ^ (r & 7)) << 4));
                }
                unsigned bfr[2][4];
#pragma unroll
                for (int ntp = 0; ntp < 2; ntp++) {
                    int r = wns + ntp * 16 + b_row;
                    ldsm_x4(bfr[ntp], Bs + r * 128 + ((gB ^ (r & 7)) << 4));
                }
#pragma unroll
                for (int ntp = 0; ntp < 2; ntp++) {
#pragma unroll
                    for (int half = 0; half < 2; half++) {
                        unsigned bf[2] = { bfr[ntp][half * 2], bfr[ntp][half * 2 + 1] };
#pragma unroll
                        for (int mt = 0; mt < 2; mt++)
                            mma_tf32(sacc[mt][ntp * 2 + half], af[mt], bf);
                    }
                }
            }
            __syncthreads();
        }

        // mask + decay -> Ss (swz256)
#pragma unroll
        for (int mt = 0; mt < 2; mt++) {
#pragma unroll
            for (int nt = 0; nt < 4; nt++) {
#pragma unroll
                for (int e = 0; e < 4; e++) {
                    int r  = wm + mt * 16 + gq + (e >> 1) * 8;
                    int cl = wns + nt * 8 + tq * 2 + (e & 1);
                    int s  = sh * 64 + cl;
                    float w = (r >= s) ? expf(lam * (float)(r - s)) : 0.0f;
                    uint32_t off = r * 256 + (((cl >> 2) ^ (r & 7)) << 4) + (cl & 3) * 4;
                    *(unsigned*)(smemc + CO_SS + off) = f2tf(sacc[mt][nt][e] * w);
                }
            }
        }
        // V^T tile (transposed scatter, swz256)
#pragma unroll
        for (int it = 0; it < 8; it++) {
            int id = it * 256 + tid;
            int n4 = id & 31;
            int i  = id >> 5;                 // 0..63
            int gI = i >> 2, wI = (i & 3) * 4;
            float4 v = *(const float4*)(Vb + (size_t)(sh * 64 + i) * VDIM + n4 * 4);
            const float vv[4] = {v.x, v.y, v.z, v.w};
#pragma unroll
            for (int e = 0; e < 4; e++) {
                int row = n4 * 4 + e;
                uint32_t off = row * 256 + ((gI ^ (row & 7)) << 4) + wI;
                *(unsigned*)(smemc + CO_VT + off) = f2tf(vv[e]);
            }
        }
        __syncthreads();

        // O += Ss @ Vt (k = 64)
#pragma unroll
        for (int k8 = 0; k8 < 8; k8++) {
            const int gA = k8 * 2 + a_gsel;
            const int gB = k8 * 2 + b_gsel;
            unsigned af[2][4];
#pragma unroll
            for (int mt = 0; mt < 2; mt++) {
                int r = wm + mt * 16 + a_row;
                ldsm_x4(af[mt], Ss + r * 256 + ((gA ^ (r & 7)) << 4));
            }
            unsigned bfr[4][4];
#pragma unroll
            for (int ntp = 0; ntp < 4; ntp++) {
                int r = wn + ntp * 16 + b_row;
                ldsm_x4(bfr[ntp], Vt + r * 256 + ((gB ^ (r & 7)) << 4));
            }
#pragma unroll
            for (int ntp = 0; ntp < 4; ntp++) {
#pragma unroll
                for (int half = 0; half < 2; half++) {
                    unsigned bf[2] = { bfr[ntp][half * 2], bfr[ntp][half * 2 + 1] };
#pragma unroll
                    for (int mt = 0; mt < 2; mt++)
                        mma_tf32(oacc[mt][ntp * 2 + half], af[mt], bf);
                }
            }
        }
        __syncthreads();
    }

#pragma unroll
    for (int mt = 0; mt < 2; mt++) {
        int r0 = wm + mt * 16 + gq;
#pragma unroll
        for (int nt = 0; nt < 8; nt++) {
            int cc = h * DV + dvt * 128 + wn + nt * 8 + tq * 2;
            size_t row = (size_t)(rowbase + r0);
            *(float2*)(g_o + row * VDIM + cc) =
                make_float2(oacc[mt][nt][0], oacc[mt][nt][1]);
            *(float2*)(g_o + (row + 8) * VDIM + cc) =
                make_float2(oacc[mt][nt][2], oacc[mt][nt][3]);
        }
    }
}

// ---------------------------------------------------------------------------
// RMSNorm * g_norm_w * silu(g); writes tf32-rounded o (feeds out_gemm).
// ---------------------------------------------------------------------------
__global__ __launch_bounds__(256) void gate_kernel(const float* __restrict__ gw)
{
    __shared__ float ws[8];
    const int blk = blockIdx.x;
    const int tid = threadIdx.x;
    const size_t base = (size_t)(blk >> 2) * VDIM + (size_t)(blk & 3) * DV;

    float2 o2 = *(float2*)(g_o + base + tid * 2);
    float p = o2.x * o2.x + o2.y * o2.y;
#pragma unroll
    for (int off = 16; off > 0; off >>= 1) p += __shfl_xor_sync(0xffffffffu, p, off);
    if ((tid & 31) == 0) ws[tid >> 5] = p;
    __syncthreads();
    float tot = ws[0] + ws[1] + ws[2] + ws[3] + ws[4] + ws[5] + ws[6] + ws[7];
    float rms = rsqrtf(tot * (1.0f / (float)DV) + 1e-5f);

    const int c = tid * 2;
    float2 g2 = *(const float2*)(g_g + base + c);
    float s0 = g2.x / (1.0f + expf(-g2.x));
    float s1 = g2.y / (1.0f + expf(-g2.y));
    o2.x = roundtf(o2.x * rms * gw[c] * s0);
    o2.y = roundtf(o2.y * rms * gw[c + 1] * s1);
    *(float2*)(g_o + base + c) = o2;
}

// ---------------------------------------------------------------------------
extern "C" void kernel_launch(void* const* d_in, const int* in_sizes, int n_in,
                              void* d_out, int out_size)
{
    const float* x  = (const float*)d_in[0];
    const float* Wq = (const float*)d_in[1];
    const float* Wk = (const float*)d_in[2];
    const float* Wv = (const float*)d_in[3];
    const float* Wg = (const float*)d_in[4];
    const float* Wo = (const float*)d_in[5];
    const float* gw = (const float*)d_in[6];
    float* out = (float*)d_out;

    cudaFuncSetAttribute(proj_gemm, cudaFuncAttributeMaxDynamicSharedMemorySize, GEMM_SMEM);
    cudaFuncSetAttribute(out_gemm,  cudaFuncAttributeMaxDynamicSharedMemorySize, GEMM_SMEM);
    cudaFuncSetAttribute(chunk_kv,  cudaFuncAttributeMaxDynamicSharedMemorySize, KV_SMEM);
    cudaFuncSetAttribute(chunk_out, cudaFuncAttributeMaxDynamicSharedMemorySize, CO_SMEM);

    // Pre-round all inputs to tf32 in one launch
    round_all<<<12288, 256>>>(x, Wq, Wk, Wv, Wg, Wo);

    // Fused projections
    dim3 gp(48, 32);
    proj_gemm<<<gp, 256, GEMM_SMEM>>>();

    rope_kernel<<<(NB * T_SEQ * NH * 128) / 256, 256>>>();

    dim3 ga(8, NCH, NB * NH);
    chunk_kv<<<ga, 256, KV_SMEM>>>();

    state_scan<<<1024, 256>>>();

    dim3 gc(4, NCH, NB * NH);
    chunk_out<<<gc, 256, CO_SMEM>>>();

    gate_kernel<<<MROWS * NH, 256>>>(gw);

    dim3 go(8, 32);
    out_gemm<<<go, 256, GEMM_SMEM>>>(out);
}

// round 13
// speedup vs baseline: 1.0706x; 1.0706x over previous
#include <cuda_runtime.h>
#include <math.h>
#include <stdint.h>

// Problem constants
constexpr int T_SEQ  = 2048;
constexpr int NB     = 2;
constexpr int NH     = 4;
constexpr int DK     = 256;
constexpr int DV     = 512;
constexpr int DMODEL = 1024;
constexpr int KDIM   = NH * DK;    // 1024
constexpr int VDIM   = NH * DV;    // 2048
constexpr int MROWS  = NB * T_SEQ; // 4096
constexpr int CHK    = 128;
constexpr int NCH    = T_SEQ / CHK; // 16
constexpr int STSZ   = DV * DK;     // 131072

// Scratch (device globals; no allocations allowed)
__device__ __align__(128) float g_q[MROWS * KDIM];
__device__ __align__(128) float g_k[MROWS * KDIM];
__device__ __align__(128) float g_v[MROWS * VDIM];
__device__ __align__(128) float g_g[MROWS * VDIM];
__device__ __align__(128) float g_o[MROWS * VDIM];
__device__ __align__(128) float g_x[MROWS * DMODEL];         // rounded x
__device__ __align__(128) float g_w[8 * 1024 * 1024];        // rounded weights
__device__ __align__(128) float g_state[NB * NH * NCH * STSZ];

// weight offsets in g_w (floats)
constexpr long long WQ_OFF = 0;
constexpr long long WK_OFF = 1048576;
constexpr long long WK2_OFF = 1310720;
constexpr long long WV_OFF = 2097152;
constexpr long long WG_OFF = 4194304;
constexpr long long WO_OFF = 6291456;

__device__ __forceinline__ unsigned f2tf(float f) {
    unsigned u;
    asm("cvt.rna.tf32.f32 %0, %1;" : "=r"(u) : "f"(f));
    return u;
}
__device__ __forceinline__ float roundtf(float f) { return __uint_as_float(f2tf(f)); }

__device__ __forceinline__ void mma_tf32(float* c, const unsigned* a, const unsigned* b) {
    asm volatile(
        "mma.sync.aligned.m16n8k8.row.col.f32.tf32.tf32.f32 "
        "{%0,%1,%2,%3}, {%4,%5,%6,%7}, {%8,%9}, {%0,%1,%2,%3};\n"
        : "+f"(c[0]), "+f"(c[1]), "+f"(c[2]), "+f"(c[3])
        : "r"(a[0]), "r"(a[1]), "r"(a[2]), "r"(a[3]), "r"(b[0]), "r"(b[1]));
}

__device__ __forceinline__ void ldsm_x4(unsigned* r, uint32_t addr) {
    asm volatile("ldmatrix.sync.aligned.m8n8.x4.shared.b16 {%0,%1,%2,%3}, [%4];"
                 : "=r"(r[0]), "=r"(r[1]), "=r"(r[2]), "=r"(r[3]) : "r"(addr));
}

__device__ __forceinline__ float head_lam(int h) {
    return logf(1.0f - exp2f(-5.0f - (float)h));
}

__device__ __forceinline__ void cpasync16(unsigned dst, const void* src) {
    asm volatile("cp.async.cg.shared.global [%0], [%1], 16;\n" :: "r"(dst), "l"(src));
}
__device__ __forceinline__ void cp_commit() {
    asm volatile("cp.async.commit_group;\n" ::: "memory");
}
__device__ __forceinline__ void cp_wait1() {
    asm volatile("cp.async.wait_group 1;\n" ::: "memory");
}
__device__ __forceinline__ uint32_t smem_u32(const void* p) {
    uint32_t a;
    asm("{ .reg .u64 t; cvta.to.shared.u64 t, %1; cvt.u32.u64 %0, t; }" : "=r"(a) : "l"(p));
    return a;
}

// ---------------------------------------------------------------------------
// Fused rounding copy for all 6 inputs (one launch).
// ---------------------------------------------------------------------------
__global__ __launch_bounds__(256) void round_all(
    const float* __restrict__ x,  const float* __restrict__ wq,
    const float* __restrict__ wk, const float* __restrict__ wv,
    const float* __restrict__ wg, const float* __restrict__ wo)
{
    int i = blockIdx.x * 256 + threadIdx.x;
    const float* src; float* dst; int off;
    if      (i < 1048576) { src = x;  dst = g_x;          off = i; }
    else if (i < 1310720) { src = wq; dst = g_w + WQ_OFF; off = i - 1048576; }
    else if (i < 1572864) { src = wk; dst = g_w + WK_OFF; off = i - 1310720; }
    else if (i < 2097152) { src = wv; dst = g_w + WV_OFF; off = i - 1572864; }
    else if (i < 2621440) { src = wg; dst = g_w + WG_OFF; off = i - 2097152; }
    else                  { src = wo; dst = g_w + WO_OFF; off = i - 2621440; }
    float4 v = ((const float4*)src)[off];
    ((float4*)dst)[off] = make_float4(roundtf(v.x), roundtf(v.y),
                                      roundtf(v.z), roundtf(v.w));
}

// ---------------------------------------------------------------------------
// TF32 GEMM, ldmatrix fragments, 3-stage cp.async, ONE sync per k-chunk.
// CTA tile 128x128, BK=32, 8 warps (4m x 2n), warp 32x64.
// ---------------------------------------------------------------------------
constexpr int AT_B   = 128 * 128;           // 16 KB tile
constexpr int STG_B  = 2 * AT_B;            // 32 KB per stage
constexpr int GEMM_SMEM = 3 * STG_B;        // 98304 bytes

__device__ __forceinline__ void gemm_pipe(
    const float* __restrict__ Ab, const float* __restrict__ Wb,
    float* __restrict__ Cb, int ldc, int K, int roundC, char* smem)
{
    const int tid  = threadIdx.x;
    const int lane = tid & 31;
    const int wid  = tid >> 5;
    const int wm = (wid & 3) * 32;
    const int wn = (wid >> 2) * 64;
    const int gq = lane >> 2;
    const int tq = lane & 3;
    const int nk = K >> 5;
    const uint32_t sa = smem_u32(smem);

    const int a_row  = (lane & 7) + ((lane >> 3) & 1) * 8;
    const int a_gsel = lane >> 4;
    const int b_row  = (lane & 7) + (lane >> 4) * 8;
    const int b_gsel = (lane >> 3) & 1;

    float acc[2][8][4];
#pragma unroll
    for (int mt = 0; mt < 2; mt++)
#pragma unroll
        for (int nt = 0; nt < 8; nt++)
#pragma unroll
            for (int e = 0; e < 4; e++) acc[mt][nt][e] = 0.0f;

    auto cp_chunk = [&](int c) {
        uint32_t ab = sa + (c % 3) * STG_B;
        uint32_t bb = ab + AT_B;
        const float* Ap = Ab + c * 32;
        const float* Bp = Wb + c * 32;
#pragma unroll
        for (int i = 0; i < 4; i++) {
            int id = i * 256 + tid;
            int row = id >> 3, g = id & 7;
            cpasync16(ab + row * 128 + ((g ^ (row & 7)) << 4),
                      Ap + (size_t)row * K + g * 4);
        }
#pragma unroll
        for (int i = 0; i < 4; i++) {
            int id = i * 256 + tid;
            int row = id >> 3, g = id & 7;
            cpasync16(bb + row * 128 + ((g ^ (row & 7)) << 4),
                      Bp + (size_t)row * K + g * 4);
        }
        cp_commit();
    };

    cp_chunk(0); cp_chunk(1);

    for (int j = 0; j < nk; j++) {
        cp_wait1();
        __syncthreads();
        if (j + 2 < nk) cp_chunk(j + 2); else cp_commit();

        uint32_t ab = sa + (j % 3) * STG_B;
        uint32_t bb = ab + AT_B;
#pragma unroll
        for (int k8 = 0; k8 < 4; k8++) {
            const int gA = k8 * 2 + a_gsel;
            const int gB = k8 * 2 + b_gsel;
            unsigned af[2][4];
#pragma unroll
            for (int mt = 0; mt < 2; mt++) {
                int r = wm + mt * 16 + a_row;
                ldsm_x4(af[mt], ab + r * 128 + ((gA ^ (r & 7)) << 4));
            }
            unsigned bfr[4][4];
#pragma unroll
            for (int ntp = 0; ntp < 4; ntp++) {
                int r = wn + ntp * 16 + b_row;
                ldsm_x4(bfr[ntp], bb + r * 128 + ((gB ^ (r & 7)) << 4));
            }
#pragma unroll
            for (int ntp = 0; ntp < 4; ntp++) {
#pragma unroll
                for (int half = 0; half < 2; half++) {
                    unsigned bf[2] = { bfr[ntp][half * 2], bfr[ntp][half * 2 + 1] };
#pragma unroll
                    for (int mt = 0; mt < 2; mt++)
                        mma_tf32(acc[mt][ntp * 2 + half], af[mt], bf);
                }
            }
        }
    }

#pragma unroll
    for (int mt = 0; mt < 2; mt++) {
        int r0 = wm + mt * 16 + gq;
#pragma unroll
        for (int nt = 0; nt < 8; nt++) {
            int cc = wn + nt * 8 + tq * 2;
            float2 v0 = make_float2(acc[mt][nt][0], acc[mt][nt][1]);
            float2 v1 = make_float2(acc[mt][nt][2], acc[mt][nt][3]);
            if (roundC) {
                v0.x = roundtf(v0.x); v0.y = roundtf(v0.y);
                v1.x = roundtf(v1.x); v1.y = roundtf(v1.y);
            }
            *(float2*)(Cb + (size_t)r0 * ldc + cc)       = v0;
            *(float2*)(Cb + (size_t)(r0 + 8) * ldc + cc) = v1;
        }
    }
}

// Fused projections: x @ {Wq,Wk,Wv,Wg}^T. grid (48, 32).
__global__ __launch_bounds__(256, 2) void proj_gemm()
{
    extern __shared__ char smem[];
    const int bnx = blockIdx.x;
    const int bm  = blockIdx.y * 128;

    const float* Wb; float* Cc; int ldc, col, roundC = 0;
    if (bnx < 8)       { Wb = g_w + WQ_OFF; Cc = g_q; ldc = 1024; col = bnx * 128; }
    else if (bnx < 16) { Wb = g_w + WK_OFF; Cc = g_k; ldc = 1024; col = (bnx - 8) * 128; }
    else if (bnx < 32) { Wb = g_w + WV_OFF; Cc = g_v; ldc = 2048; col = (bnx - 16) * 128; roundC = 1; }
    else               { Wb = g_w + WG_OFF; Cc = g_g; ldc = 2048; col = (bnx - 32) * 128; }

    gemm_pipe(g_x + (size_t)bm * DMODEL, Wb + (size_t)col * DMODEL,
              Cc + (size_t)bm * ldc + col, ldc, DMODEL, roundC, smem);
}

// Output projection: (g_o rounded) @ Wo^T -> out. grid (8, 32).
__global__ __launch_bounds__(256, 2) void out_gemm(float* __restrict__ out)
{
    extern __shared__ char smem[];
    const int bn = blockIdx.x * 128;
    const int bm = blockIdx.y * 128;
    gemm_pipe(g_o + (size_t)bm * VDIM, g_w + WO_OFF + (size_t)bn * VDIM,
              out + (size_t)bm * DMODEL + bn, DMODEL, VDIM, 0, smem);
}

// ---------------------------------------------------------------------------
// RoPE (in place on g_q, g_k) + q scale by dk^-0.5 (fp32 path as reference).
// ---------------------------------------------------------------------------
__global__ __launch_bounds__(256) void rope_kernel()
{
    int idx = blockIdx.x * 256 + threadIdx.x;
    int i  = idx & 127;
    int h  = (idx >> 7) & 3;
    int bt = idx >> 9;
    int t  = bt & (T_SEQ - 1);
    size_t base = (size_t)bt * KDIM + h * DK;

    float e    = (float)(2 * i) * (1.0f / 256.0f);
    float invf = 1.0f / powf(10000.0f, e);
    float ang  = (float)t * invf;
    float sn, cs;
    sincosf(ang, &sn, &cs);

    float q1 = g_q[base + i], q2 = g_q[base + 128 + i];
    g_q[base + i]       = (q1 * cs - q2 * sn) * 0.0625f;
    g_q[base + 128 + i] = (q1 * sn + q2 * cs) * 0.0625f;
    float k1 = g_k[base + i], k2 = g_k[base + 128 + i];
    g_k[base + i]       = k1 * cs - k2 * sn;
    g_k[base + 128 + i] = k1 * sn + k2 * cs;
}

// ---------------------------------------------------------------------------
// Phase A: per (bh, chunk) U^T[dv, dk] = sum_i lam^(C-i) V[i,:]^T K[i,:]
// ldmatrix, 2 CTAs/SM (reg cap 128).
// ---------------------------------------------------------------------------
constexpr int KV_SMEM = 65536;

__global__ __launch_bounds__(256, 2) void chunk_kv()
{
    extern __shared__ char smemk[];
    const uint32_t sb = smem_u32(smemk);
    const uint32_t Vt = sb;
    const uint32_t Kt = sb + 32768;

    const int tid  = threadIdx.x;
    const int lane = tid & 31;
    const int wid  = tid >> 5;
    const int gq = lane >> 2;
    const int tq = lane & 3;
    const int wm = (wid & 3) * 32;
    const int wn = (wid >> 2) * 64;

    const int a_row  = (lane & 7) + ((lane >> 3) & 1) * 8;
    const int a_gsel = lane >> 4;
    const int b_row  = (lane & 7) + (lane >> 4) * 8;
    const int b_gsel = (lane >> 3) & 1;

    const int dvt = blockIdx.x & 3;
    const int dkt = blockIdx.x >> 2;
    const int c   = blockIdx.y;
    const int bh  = blockIdx.z;
    const int b = bh >> 2, h = bh & 3;
    const float lam = head_lam(h);

    const int rowbase = b * T_SEQ + c * CHK;
    const float* Vb = g_v + (size_t)rowbase * VDIM + h * DV + dvt * 128;
    const float* Kb = g_k + (size_t)rowbase * KDIM + h * DK + dkt * 128;

    float acc[2][8][4];
#pragma unroll
    for (int mt = 0; mt < 2; mt++)
#pragma unroll
        for (int nt = 0; nt < 8; nt++)
#pragma unroll
            for (int e = 0; e < 4; e++) acc[mt][nt][e] = 0.0f;

    for (int sh = 0; sh < 2; sh++) {
#pragma unroll
        for (int it = 0; it < 8; it++) {
            int id = it * 256 + tid;
            int n4 = id & 31;
            int i  = id >> 5;              // 0..63
            int gI = i >> 2, wI = (i & 3) * 4;
            float4 v = *(const float4*)(Vb + (size_t)(sh * 64 + i) * VDIM + n4 * 4);
            float w = expf(lam * (float)(CHK - (sh * 64 + i)));
            float4 kv = *(const float4*)(Kb + (size_t)(sh * 64 + i) * KDIM + n4 * 4);
            const float vv[4] = {v.x, v.y, v.z, v.w};
            const float kk4[4] = {kv.x * w, kv.y * w, kv.z * w, kv.w * w};
#pragma unroll
            for (int e = 0; e < 4; e++) {
                int row = n4 * 4 + e;
                uint32_t off = row * 256 + ((gI ^ (row & 7)) << 4) + wI;
                *(unsigned*)(smemk + off)         = f2tf(vv[e]);
                *(unsigned*)(smemk + 32768 + off) = f2tf(kk4[e]);
            }
        }
        __syncthreads();
#pragma unroll
        for (int k8 = 0; k8 < 8; k8++) {
            const int gA = k8 * 2 + a_gsel;
            const int gB = k8 * 2 + b_gsel;
            unsigned af[2][4];
#pragma unroll
            for (int mt = 0; mt < 2; mt++) {
                int r = wm + mt * 16 + a_row;
                ldsm_x4(af[mt], Vt + r * 256 + ((gA ^ (r & 7)) << 4));
            }
            unsigned bfr[4][4];
#pragma unroll
            for (int ntp = 0; ntp < 4; ntp++) {
                int r = wn + ntp * 16 + b_row;
                ldsm_x4(bfr[ntp], Kt + r * 256 + ((gB ^ (r & 7)) << 4));
            }
#pragma unroll
            for (int ntp = 0; ntp < 4; ntp++) {
#pragma unroll
                for (int half = 0; half < 2; half++) {
                    unsigned bf[2] = { bfr[ntp][half * 2], bfr[ntp][half * 2 + 1] };
#pragma unroll
                    for (int mt = 0; mt < 2; mt++)
                        mma_tf32(acc[mt][ntp * 2 + half], af[mt], bf);
                }
            }
        }
        __syncthreads();
    }

    float* St = g_state + (size_t)(bh * NCH + c) * STSZ;
#pragma unroll
    for (int mt = 0; mt < 2; mt++) {
        int r0 = dvt * 128 + wm + mt * 16 + gq;
#pragma unroll
        for (int nt = 0; nt < 8; nt++) {
            int cc = dkt * 128 + wn + nt * 8 + tq * 2;
            *(float2*)(St + (size_t)r0 * DK + cc)       = make_float2(acc[mt][nt][0], acc[mt][nt][1]);
            *(float2*)(St + (size_t)(r0 + 8) * DK + cc) = make_float2(acc[mt][nt][2], acc[mt][nt][3]);
        }
    }
}

// ---------------------------------------------------------------------------
// Phase B: prefix scan; stores tf32-rounded State snapshots (accum fp32).
// ---------------------------------------------------------------------------
__global__ __launch_bounds__(256) void state_scan()
{
    int tid4 = blockIdx.x * 256 + threadIdx.x;
    int bh   = tid4 >> 15;
    int off  = (tid4 & 32767) * 4;
    const float d = expf(head_lam(bh & 3) * (float)CHK);

    float* base = g_state + (size_t)bh * NCH * STSZ + off;
    float4 s = make_float4(0.f, 0.f, 0.f, 0.f);
#pragma unroll
    for (int c = 0; c < NCH; c++) {
        float4 u = *(float4*)(base + (size_t)c * STSZ);
        *(float4*)(base + (size_t)c * STSZ) =
            make_float4(roundtf(s.x), roundtf(s.y), roundtf(s.z), roundtf(s.w));
        s.x = d * s.x + u.x;
        s.y = d * s.y + u.y;
        s.z = d * s.z + u.z;
        s.w = d * s.w + u.w;
    }
}

// ---------------------------------------------------------------------------
// Phase C: O[128,128] = Qhat @ State^T + (mask . Q K^T) @ V, ldmatrix,
// 2 CTAs/SM (reg cap 128).
// ---------------------------------------------------------------------------
constexpr int CO_QS = 0;
constexpr int CO_BS = 16384;
constexpr int CO_SS = 32768;
constexpr int CO_VT = 65536;
constexpr int CO_SMEM = 98304;

__global__ __launch_bounds__(256, 2) void chunk_out()
{
    extern __shared__ char smemc[];
    const uint32_t sb = smem_u32(smemc);
    const uint32_t Qs = sb + CO_QS;
    const uint32_t Bs = sb + CO_BS;
    const uint32_t Ss = sb + CO_SS;
    const uint32_t Vt = sb + CO_VT;

    const int tid  = threadIdx.x;
    const int lane = tid & 31;
    const int wid  = tid >> 5;
    const int gq = lane >> 2;
    const int tq = lane & 3;
    const int wm  = (wid & 3) * 32;
    const int wn  = (wid >> 2) * 64;
    const int wns = (wid >> 2) * 32;

    const int a_row  = (lane & 7) + ((lane >> 3) & 1) * 8;
    const int a_gsel = lane >> 4;
    const int b_row  = (lane & 7) + (lane >> 4) * 8;
    const int b_gsel = (lane >> 3) & 1;

    const int dvt = blockIdx.x;
    const int c   = blockIdx.y;
    const int bh  = blockIdx.z;
    const int b = bh >> 2, h = bh & 3;
    const float lam = head_lam(h);

    const int rowbase = b * T_SEQ + c * CHK;
    const float* Qb = g_q + (size_t)rowbase * KDIM + h * DK;
    const float* Kb = g_k + (size_t)rowbase * KDIM + h * DK;
    const float* Vb = g_v + (size_t)rowbase * VDIM + h * DV + dvt * 128;
    const float* St = g_state + (size_t)(bh * NCH + c) * STSZ + (size_t)dvt * 128 * DK;

    float oacc[2][8][4];
#pragma unroll
    for (int mt = 0; mt < 2; mt++)
#pragma unroll
        for (int nt = 0; nt < 8; nt++)
#pragma unroll
            for (int e = 0; e < 4; e++) oacc[mt][nt][e] = 0.0f;

    // ---------------- cross term: O += Qhat @ State^T ----------------
    for (int kc = 0; kc < DK; kc += 32) {
#pragma unroll
        for (int it = 0; it < 4; it++) {
            int id  = it * 256 + tid;
            int row = id >> 3;
            int g   = id & 7;
            uint32_t off = row * 128 + ((g ^ (row & 7)) << 4);
            float w = expf(lam * (float)row);
            float4 q = *(const float4*)(Qb + (size_t)row * KDIM + kc + g * 4);
            *(uint4*)(smemc + CO_QS + off) =
                make_uint4(f2tf(q.x * w), f2tf(q.y * w), f2tf(q.z * w), f2tf(q.w * w));
            float4 s = *(const float4*)(St + (size_t)row * DK + kc + g * 4);
            *(uint4*)(smemc + CO_BS + off) =
                make_uint4(f2tf(s.x), f2tf(s.y), f2tf(s.z), f2tf(s.w));
        }
        __syncthreads();
#pragma unroll
        for (int k8 = 0; k8 < 4; k8++) {
            const int gA = k8 * 2 + a_gsel;
            const int gB = k8 * 2 + b_gsel;
            unsigned af[2][4];
#pragma unroll
            for (int mt = 0; mt < 2; mt++) {
                int r = wm + mt * 16 + a_row;
                ldsm_x4(af[mt], Qs + r * 128 + ((gA ^ (r & 7)) << 4));
            }
            unsigned bfr[4][4];
#pragma unroll
            for (int ntp = 0; ntp < 4; ntp++) {
                int r = wn + ntp * 16 + b_row;
                ldsm_x4(bfr[ntp], Bs + r * 128 + ((gB ^ (r & 7)) << 4));
            }
#pragma unroll
            for (int ntp = 0; ntp < 4; ntp++) {
#pragma unroll
                for (int half = 0; half < 2; half++) {
                    unsigned bf[2] = { bfr[ntp][half * 2], bfr[ntp][half * 2 + 1] };
#pragma unroll
                    for (int mt = 0; mt < 2; mt++)
                        mma_tf32(oacc[mt][ntp * 2 + half], af[mt], bf);
                }
            }
        }
        __syncthreads();
    }

    // ---------------- intra term, two 64-key halves ----------------
    for (int sh = 0; sh < 2; sh++) {
        float sacc[2][4][4];
#pragma unroll
        for (int mt = 0; mt < 2; mt++)
#pragma unroll
            for (int nt = 0; nt < 4; nt++)
#pragma unroll
                for (int e = 0; e < 4; e++) sacc[mt][nt][e] = 0.0f;

        for (int kc = 0; kc < DK; kc += 32) {
#pragma unroll
            for (int it = 0; it < 4; it++) {
                int id  = it * 256 + tid;
                int row = id >> 3;
                int g   = id & 7;
                uint32_t off = row * 128 + ((g ^ (row & 7)) << 4);
                float4 q = *(const float4*)(Qb + (size_t)row * KDIM + kc + g * 4);
                *(uint4*)(smemc + CO_QS + off) =
                    make_uint4(f2tf(q.x), f2tf(q.y), f2tf(q.z), f2tf(q.w));
            }
#pragma unroll
            for (int it = 0; it < 2; it++) {
                int id  = it * 256 + tid;
                int row = id >> 3;             // 0..63
                int g   = id & 7;
                uint32_t off = row * 128 + ((g ^ (row & 7)) << 4);
                float4 kv = *(const float4*)(Kb + (size_t)(sh * 64 + row) * KDIM + kc + g * 4);
                *(uint4*)(smemc + CO_BS + off) =
                    make_uint4(f2tf(kv.x), f2tf(kv.y), f2tf(kv.z), f2tf(kv.w));
            }
            __syncthreads();
#pragma unroll
            for (int k8 = 0; k8 < 4; k8++) {
                const int gA = k8 * 2 + a_gsel;
                const int gB = k8 * 2 + b_gsel;
                unsigned af[2][4];
#pragma unroll
                for (int mt = 0; mt < 2; mt++) {
                    int r = wm + mt * 16 + a_row;
                    ldsm_x4(af[mt], Qs + r * 128 + ((gA ^ (r & 7)) << 4));
                }
                unsigned bfr[2][4];
#pragma unroll
                for (int ntp = 0; ntp < 2; ntp++) {
                    int r = wns + ntp * 16 + b_row;
                    ldsm_x4(bfr[ntp], Bs + r * 128 + ((gB ^ (r & 7)) << 4));
                }
#pragma unroll
                for (int ntp = 0; ntp < 2; ntp++) {
#pragma unroll
                    for (int half = 0; half < 2; half++) {
                        unsigned bf[2] = { bfr[ntp][half * 2], bfr[ntp][half * 2 + 1] };
#pragma unroll
                        for (int mt = 0; mt < 2; mt++)
                            mma_tf32(sacc[mt][ntp * 2 + half], af[mt], bf);
                    }
                }
            }
            __syncthreads();
        }

        // mask + decay -> Ss (swz256)
#pragma unroll
        for (int mt = 0; mt < 2; mt++) {
#pragma unroll
            for (int nt = 0; nt < 4; nt++) {
#pragma unroll
                for (int e = 0; e < 4; e++) {
                    int r  = wm + mt * 16 + gq + (e >> 1) * 8;
                    int cl = wns + nt * 8 + tq * 2 + (e & 1);
                    int s  = sh * 64 + cl;
                    float w = (r >= s) ? expf(lam * (float)(r - s)) : 0.0f;
                    uint32_t off = r * 256 + (((cl >> 2) ^ (r & 7)) << 4) + (cl & 3) * 4;
                    *(unsigned*)(smemc + CO_SS + off) = f2tf(sacc[mt][nt][e] * w);
                }
            }
        }
        // V^T tile (transposed scatter, swz256)
#pragma unroll
        for (int it = 0; it < 8; it++) {
            int id = it * 256 + tid;
            int n4 = id & 31;
            int i  = id >> 5;                 // 0..63
            int gI = i >> 2, wI = (i & 3) * 4;
            float4 v = *(const float4*)(Vb + (size_t)(sh * 64 + i) * VDIM + n4 * 4);
            const float vv[4] = {v.x, v.y, v.z, v.w};
#pragma unroll
            for (int e = 0; e < 4; e++) {
                int row = n4 * 4 + e;
                uint32_t off = row * 256 + ((gI ^ (row & 7)) << 4) + wI;
                *(unsigned*)(smemc + CO_VT + off) = f2tf(vv[e]);
            }
        }
        __syncthreads();

        // O += Ss @ Vt (k = 64)
#pragma unroll
        for (int k8 = 0; k8 < 8; k8++) {
            const int gA = k8 * 2 + a_gsel;
            const int gB = k8 * 2 + b_gsel;
            unsigned af[2][4];
#pragma unroll
            for (int mt = 0; mt < 2; mt++) {
                int r = wm + mt * 16 + a_row;
                ldsm_x4(af[mt], Ss + r * 256 + ((gA ^ (r & 7)) << 4));
            }
            unsigned bfr[4][4];
#pragma unroll
            for (int ntp = 0; ntp < 4; ntp++) {
                int r = wn + ntp * 16 + b_row;
                ldsm_x4(bfr[ntp], Vt + r * 256 + ((gB ^ (r & 7)) << 4));
            }
#pragma unroll
            for (int ntp = 0; ntp < 4; ntp++) {
#pragma unroll
                for (int half = 0; half < 2; half++) {
                    unsigned bf[2] = { bfr[ntp][half * 2], bfr[ntp][half * 2 + 1] };
#pragma unroll
                    for (int mt = 0; mt < 2; mt++)
                        mma_tf32(oacc[mt][ntp * 2 + half], af[mt], bf);
                }
            }
        }
        __syncthreads();
    }

#pragma unroll
    for (int mt = 0; mt < 2; mt++) {
        int r0 = wm + mt * 16 + gq;
#pragma unroll
        for (int nt = 0; nt < 8; nt++) {
            int cc = h * DV + dvt * 128 + wn + nt * 8 + tq * 2;
            size_t row = (size_t)(rowbase + r0);
            *(float2*)(g_o + row * VDIM + cc) =
                make_float2(oacc[mt][nt][0], oacc[mt][nt][1]);
            *(float2*)(g_o + (row + 8) * VDIM + cc) =
                make_float2(oacc[mt][nt][2], oacc[mt][nt][3]);
        }
    }
}

// ---------------------------------------------------------------------------
// RMSNorm * g_norm_w * silu(g); writes tf32-rounded o (feeds out_gemm).
// ---------------------------------------------------------------------------
__global__ __launch_bounds__(256) void gate_kernel(const float* __restrict__ gw)
{
    __shared__ float ws[8];
    const int blk = blockIdx.x;
    const int tid = threadIdx.x;
    const size_t base = (size_t)(blk >> 2) * VDIM + (size_t)(blk & 3) * DV;

    float2 o2 = *(float2*)(g_o + base + tid * 2);
    float p = o2.x * o2.x + o2.y * o2.y;
#pragma unroll
    for (int off = 16; off > 0; off >>= 1) p += __shfl_xor_sync(0xffffffffu, p, off);
    if ((tid & 31) == 0) ws[tid >> 5] = p;
    __syncthreads();
    float tot = ws[0] + ws[1] + ws[2] + ws[3] + ws[4] + ws[5] + ws[6] + ws[7];
    float rms = rsqrtf(tot * (1.0f / (float)DV) + 1e-5f);

    const int c = tid * 2;
    float2 g2 = *(const float2*)(g_g + base + c);
    float s0 = g2.x / (1.0f + expf(-g2.x));
    float s1 = g2.y / (1.0f + expf(-g2.y));
    o2.x = roundtf(o2.x * rms * gw[c] * s0);
    o2.y = roundtf(o2.y * rms * gw[c + 1] * s1);
    *(float2*)(g_o + base + c) = o2;
}

// ---------------------------------------------------------------------------
extern "C" void kernel_launch(void* const* d_in, const int* in_sizes, int n_in,
                              void* d_out, int out_size)
{
    const float* x  = (const float*)d_in[0];
    const float* Wq = (const float*)d_in[1];
    const float* Wk = (const float*)d_in[2];
    const float* Wv = (const float*)d_in[3];
    const float* Wg = (const float*)d_in[4];
    const float* Wo = (const float*)d_in[5];
    const float* gw = (const float*)d_in[6];
    float* out = (float*)d_out;

    cudaFuncSetAttribute(proj_gemm, cudaFuncAttributeMaxDynamicSharedMemorySize, GEMM_SMEM);
    cudaFuncSetAttribute(out_gemm,  cudaFuncAttributeMaxDynamicSharedMemorySize, GEMM_SMEM);
    cudaFuncSetAttribute(chunk_kv,  cudaFuncAttributeMaxDynamicSharedMemorySize, KV_SMEM);
    cudaFuncSetAttribute(chunk_out, cudaFuncAttributeMaxDynamicSharedMemorySize, CO_SMEM);

    // Pre-round all inputs to tf32 in one launch
    round_all<<<12288, 256>>>(x, Wq, Wk, Wv, Wg, Wo);

    // Fused projections
    dim3 gp(48, 32);
    proj_gemm<<<gp, 256, GEMM_SMEM>>>();

    rope_kernel<<<(NB * T_SEQ * NH * 128) / 256, 256>>>();

    dim3 ga(8, NCH, NB * NH);
    chunk_kv<<<ga, 256, KV_SMEM>>>();

    state_scan<<<1024, 256>>>();

    dim3 gc(4, NCH, NB * NH);
    chunk_out<<<gc, 256, CO_SMEM>>>();

    gate_kernel<<<MROWS * NH, 256>>>(gw);

    dim3 go(8, 32);
    out_gemm<<<go, 256, GEMM_SMEM>>>(out);
}

// round 14
// speedup vs baseline: 1.1818x; 1.1039x over previous
#include <cuda_runtime.h>
#include <math.h>
#include <stdint.h>

// Problem constants
constexpr int T_SEQ  = 2048;
constexpr int NB     = 2;
constexpr int NH     = 4;
constexpr int DK     = 256;
constexpr int DV     = 512;
constexpr int DMODEL = 1024;
constexpr int KDIM   = NH * DK;    // 1024
constexpr int VDIM   = NH * DV;    // 2048
constexpr int MROWS  = NB * T_SEQ; // 4096
constexpr int CHK    = 128;
constexpr int NCH    = T_SEQ / CHK; // 16
constexpr int STSZ   = DV * DK;     // 131072

// Scratch (device globals; no allocations allowed)
__device__ __align__(128) float g_q[MROWS * KDIM];
__device__ __align__(128) float g_k[MROWS * KDIM];
__device__ __align__(128) float g_v[MROWS * VDIM];
__device__ __align__(128) float g_g[MROWS * VDIM];
__device__ __align__(128) float g_o[MROWS * VDIM];
__device__ __align__(128) float g_x[MROWS * DMODEL];         // rounded x
__device__ __align__(128) float g_w[8 * 1024 * 1024];        // rounded weights
__device__ __align__(128) float g_state[NB * NH * NCH * STSZ];

// weight offsets in g_w (floats)
constexpr long long WQ_OFF = 0;
constexpr long long WK_OFF = 1048576;
constexpr long long WV_OFF = 2097152;
constexpr long long WG_OFF = 4194304;
constexpr long long WO_OFF = 6291456;

__device__ __forceinline__ unsigned f2tf(float f) {
    unsigned u;
    asm("cvt.rna.tf32.f32 %0, %1;" : "=r"(u) : "f"(f));
    return u;
}
__device__ __forceinline__ float roundtf(float f) { return __uint_as_float(f2tf(f)); }

__device__ __forceinline__ void mma_tf32(float* c, const unsigned* a, const unsigned* b) {
    asm volatile(
        "mma.sync.aligned.m16n8k8.row.col.f32.tf32.tf32.f32 "
        "{%0,%1,%2,%3}, {%4,%5,%6,%7}, {%8,%9}, {%0,%1,%2,%3};\n"
        : "+f"(c[0]), "+f"(c[1]), "+f"(c[2]), "+f"(c[3])
        : "r"(a[0]), "r"(a[1]), "r"(a[2]), "r"(a[3]), "r"(b[0]), "r"(b[1]));
}

__device__ __forceinline__ void ldsm_x4(unsigned* r, uint32_t addr) {
    asm volatile("ldmatrix.sync.aligned.m8n8.x4.shared.b16 {%0,%1,%2,%3}, [%4];"
                 : "=r"(r[0]), "=r"(r[1]), "=r"(r[2]), "=r"(r[3]) : "r"(addr));
}

__device__ __forceinline__ float head_lam(int h) {
    return logf(1.0f - exp2f(-5.0f - (float)h));
}

__device__ __forceinline__ void cpasync16(unsigned dst, const void* src) {
    asm volatile("cp.async.cg.shared.global [%0], [%1], 16;\n" :: "r"(dst), "l"(src));
}
__device__ __forceinline__ void cp_commit() {
    asm volatile("cp.async.commit_group;\n" ::: "memory");
}
__device__ __forceinline__ void cp_wait1() {
    asm volatile("cp.async.wait_group 1;\n" ::: "memory");
}
__device__ __forceinline__ uint32_t smem_u32(const void* p) {
    uint32_t a;
    asm("{ .reg .u64 t; cvta.to.shared.u64 t, %1; cvt.u32.u64 %0, t; }" : "=r"(a) : "l"(p));
    return a;
}

// ---------------------------------------------------------------------------
// Fused rounding copy for all 6 inputs (one launch).
// ---------------------------------------------------------------------------
__global__ __launch_bounds__(256) void round_all(
    const float* __restrict__ x,  const float* __restrict__ wq,
    const float* __restrict__ wk, const float* __restrict__ wv,
    const float* __restrict__ wg, const float* __restrict__ wo)
{
    int i = blockIdx.x * 256 + threadIdx.x;
    const float* src; float* dst; int off;
    if      (i < 1048576) { src = x;  dst = g_x;          off = i; }
    else if (i < 1310720) { src = wq; dst = g_w + WQ_OFF; off = i - 1048576; }
    else if (i < 1572864) { src = wk; dst = g_w + WK_OFF; off = i - 1310720; }
    else if (i < 2097152) { src = wv; dst = g_w + WV_OFF; off = i - 1572864; }
    else if (i < 2621440) { src = wg; dst = g_w + WG_OFF; off = i - 2097152; }
    else                  { src = wo; dst = g_w + WO_OFF; off = i - 2621440; }
    float4 v = ((const float4*)src)[off];
    ((float4*)dst)[off] = make_float4(roundtf(v.x), roundtf(v.y),
                                      roundtf(v.z), roundtf(v.w));
}

// ---------------------------------------------------------------------------
// TF32 GEMM, ldmatrix fragments, 3-stage cp.async, ONE sync per k-chunk.
// CTA tile 128x128, BK=32, 8 warps (4m x 2n), warp 32x64.
// ---------------------------------------------------------------------------
constexpr int AT_B   = 128 * 128;           // 16 KB tile
constexpr int STG_B  = 2 * AT_B;            // 32 KB per stage
constexpr int GEMM_SMEM = 3 * STG_B;        // 98304 bytes

__device__ __forceinline__ void gemm_pipe(
    const float* __restrict__ Ab, const float* __restrict__ Wb,
    float* __restrict__ Cb, int ldc, int K, int roundC, char* smem)
{
    const int tid  = threadIdx.x;
    const int lane = tid & 31;
    const int wid  = tid >> 5;
    const int wm = (wid & 3) * 32;
    const int wn = (wid >> 2) * 64;
    const int gq = lane >> 2;
    const int tq = lane & 3;
    const int nk = K >> 5;
    const uint32_t sa = smem_u32(smem);

    const int a_row  = (lane & 7) + ((lane >> 3) & 1) * 8;
    const int a_gsel = lane >> 4;
    const int b_row  = (lane & 7) + (lane >> 4) * 8;
    const int b_gsel = (lane >> 3) & 1;

    float acc[2][8][4];
#pragma unroll
    for (int mt = 0; mt < 2; mt++)
#pragma unroll
        for (int nt = 0; nt < 8; nt++)
#pragma unroll
            for (int e = 0; e < 4; e++) acc[mt][nt][e] = 0.0f;

    auto cp_chunk = [&](int c) {
        uint32_t ab = sa + (c % 3) * STG_B;
        uint32_t bb = ab + AT_B;
        const float* Ap = Ab + c * 32;
        const float* Bp = Wb + c * 32;
#pragma unroll
        for (int i = 0; i < 4; i++) {
            int id = i * 256 + tid;
            int row = id >> 3, g = id & 7;
            cpasync16(ab + row * 128 + ((g ^ (row & 7)) << 4),
                      Ap + (size_t)row * K + g * 4);
        }
#pragma unroll
        for (int i = 0; i < 4; i++) {
            int id = i * 256 + tid;
            int row = id >> 3, g = id & 7;
            cpasync16(bb + row * 128 + ((g ^ (row & 7)) << 4),
                      Bp + (size_t)row * K + g * 4);
        }
        cp_commit();
    };

    cp_chunk(0); cp_chunk(1);

    for (int j = 0; j < nk; j++) {
        cp_wait1();
        __syncthreads();
        if (j + 2 < nk) cp_chunk(j + 2); else cp_commit();

        uint32_t ab = sa + (j % 3) * STG_B;
        uint32_t bb = ab + AT_B;
#pragma unroll
        for (int k8 = 0; k8 < 4; k8++) {
            const int gA = k8 * 2 + a_gsel;
            const int gB = k8 * 2 + b_gsel;
            unsigned af[2][4];
#pragma unroll
            for (int mt = 0; mt < 2; mt++) {
                int r = wm + mt * 16 + a_row;
                ldsm_x4(af[mt], ab + r * 128 + ((gA ^ (r & 7)) << 4));
            }
            unsigned bfr[4][4];
#pragma unroll
            for (int ntp = 0; ntp < 4; ntp++) {
                int r = wn + ntp * 16 + b_row;
                ldsm_x4(bfr[ntp], bb + r * 128 + ((gB ^ (r & 7)) << 4));
            }
#pragma unroll
            for (int ntp = 0; ntp < 4; ntp++) {
#pragma unroll
                for (int half = 0; half < 2; half++) {
                    unsigned bf[2] = { bfr[ntp][half * 2], bfr[ntp][half * 2 + 1] };
#pragma unroll
                    for (int mt = 0; mt < 2; mt++)
                        mma_tf32(acc[mt][ntp * 2 + half], af[mt], bf);
                }
            }
        }
    }

#pragma unroll
    for (int mt = 0; mt < 2; mt++) {
        int r0 = wm + mt * 16 + gq;
#pragma unroll
        for (int nt = 0; nt < 8; nt++) {
            int cc = wn + nt * 8 + tq * 2;
            float2 v0 = make_float2(acc[mt][nt][0], acc[mt][nt][1]);
            float2 v1 = make_float2(acc[mt][nt][2], acc[mt][nt][3]);
            if (roundC) {
                v0.x = roundtf(v0.x); v0.y = roundtf(v0.y);
                v1.x = roundtf(v1.x); v1.y = roundtf(v1.y);
            }
            *(float2*)(Cb + (size_t)r0 * ldc + cc)       = v0;
            *(float2*)(Cb + (size_t)(r0 + 8) * ldc + cc) = v1;
        }
    }
}

// Fused projections: x @ {Wq,Wk,Wv,Wg}^T. grid (48, 32).
__global__ __launch_bounds__(256, 2) void proj_gemm()
{
    extern __shared__ char smem[];
    const int bnx = blockIdx.x;
    const int bm  = blockIdx.y * 128;

    const float* Wb; float* Cc; int ldc, col, roundC = 0;
    if (bnx < 8)       { Wb = g_w + WQ_OFF; Cc = g_q; ldc = 1024; col = bnx * 128; }
    else if (bnx < 16) { Wb = g_w + WK_OFF; Cc = g_k; ldc = 1024; col = (bnx - 8) * 128; }
    else if (bnx < 32) { Wb = g_w + WV_OFF; Cc = g_v; ldc = 2048; col = (bnx - 16) * 128; roundC = 1; }
    else               { Wb = g_w + WG_OFF; Cc = g_g; ldc = 2048; col = (bnx - 32) * 128; }

    gemm_pipe(g_x + (size_t)bm * DMODEL, Wb + (size_t)col * DMODEL,
              Cc + (size_t)bm * ldc + col, ldc, DMODEL, roundC, smem);
}

// Output projection: (g_o rounded) @ Wo^T -> out. grid (8, 32).
__global__ __launch_bounds__(256, 2) void out_gemm(float* __restrict__ out)
{
    extern __shared__ char smem[];
    const int bn = blockIdx.x * 128;
    const int bm = blockIdx.y * 128;
    gemm_pipe(g_o + (size_t)bm * VDIM, g_w + WO_OFF + (size_t)bn * VDIM,
              out + (size_t)bm * DMODEL + bn, DMODEL, VDIM, 0, smem);
}

// ---------------------------------------------------------------------------
// RoPE (in place on g_q, g_k) + q scale by dk^-0.5 (fp32 path as reference).
// ---------------------------------------------------------------------------
__global__ __launch_bounds__(256) void rope_kernel()
{
    int idx = blockIdx.x * 256 + threadIdx.x;
    int i  = idx & 127;
    int h  = (idx >> 7) & 3;
    int bt = idx >> 9;
    int t  = bt & (T_SEQ - 1);
    size_t base = (size_t)bt * KDIM + h * DK;

    float e    = (float)(2 * i) * (1.0f / 256.0f);
    float invf = 1.0f / powf(10000.0f, e);
    float ang  = (float)t * invf;
    float sn, cs;
    sincosf(ang, &sn, &cs);

    float q1 = g_q[base + i], q2 = g_q[base + 128 + i];
    g_q[base + i]       = (q1 * cs - q2 * sn) * 0.0625f;
    g_q[base + 128 + i] = (q1 * sn + q2 * cs) * 0.0625f;
    float k1 = g_k[base + i], k2 = g_k[base + 128 + i];
    g_k[base + i]       = k1 * cs - k2 * sn;
    g_k[base + 128 + i] = k1 * sn + k2 * cs;
}

// ---------------------------------------------------------------------------
// Phase A: per (bh, chunk) U^T[dv, dk] = sum_i lam^(C-i) V[i,:]^T K[i,:]
// ldmatrix, 2 CTAs/SM. Transpose via granule-per-thread: conflict-free
// STS.128, coalesced column-strided LDG.32 (lanes span 32 consecutive rows).
// ---------------------------------------------------------------------------
constexpr int KV_SMEM = 65536;

__global__ __launch_bounds__(256, 2) void chunk_kv()
{
    extern __shared__ char smemk[];
    const uint32_t sb = smem_u32(smemk);
    const uint32_t Vt = sb;
    const uint32_t Kt = sb + 32768;

    const int tid  = threadIdx.x;
    const int lane = tid & 31;
    const int wid  = tid >> 5;
    const int gq = lane >> 2;
    const int tq = lane & 3;
    const int wm = (wid & 3) * 32;
    const int wn = (wid >> 2) * 64;

    const int a_row  = (lane & 7) + ((lane >> 3) & 1) * 8;
    const int a_gsel = lane >> 4;
    const int b_row  = (lane & 7) + (lane >> 4) * 8;
    const int b_gsel = (lane >> 3) & 1;

    const int dvt = blockIdx.x & 3;
    const int dkt = blockIdx.x >> 2;
    const int c   = blockIdx.y;
    const int bh  = blockIdx.z;
    const int b = bh >> 2, h = bh & 3;
    const float lam = head_lam(h);

    const int rowbase = b * T_SEQ + c * CHK;
    const float* Vb = g_v + (size_t)rowbase * VDIM + h * DV + dvt * 128;
    const float* Kb = g_k + (size_t)rowbase * KDIM + h * DK + dkt * 128;

    float acc[2][8][4];
#pragma unroll
    for (int mt = 0; mt < 2; mt++)
#pragma unroll
        for (int nt = 0; nt < 8; nt++)
#pragma unroll
            for (int e = 0; e < 4; e++) acc[mt][nt][e] = 0.0f;

    for (int sh = 0; sh < 2; sh++) {
        // granule-per-thread transpose: thread owns (col-granule gI, rows rr*32+lane)
#pragma unroll
        for (int g2 = 0; g2 < 2; g2++) {
            int gI = g2 * 8 + (tid >> 5);              // 0..15
            int i0 = sh * 64 + gI * 4;
            float w0 = expf(lam * (float)(CHK - (i0 + 0)));
            float w1 = expf(lam * (float)(CHK - (i0 + 1)));
            float w2 = expf(lam * (float)(CHK - (i0 + 2)));
            float w3 = expf(lam * (float)(CHK - (i0 + 3)));
#pragma unroll
            for (int rr = 0; rr < 4; rr++) {
                int r = rr * 32 + lane;
                uint32_t off = r * 256 + ((gI ^ (r & 7)) << 4);
                const float* vp = Vb + (size_t)i0 * VDIM + r;
                *(uint4*)(smemk + off) = make_uint4(
                    f2tf(vp[0]), f2tf(vp[VDIM]), f2tf(vp[2 * VDIM]), f2tf(vp[3 * VDIM]));
                const float* kp = Kb + (size_t)i0 * KDIM + r;
                *(uint4*)(smemk + 32768 + off) = make_uint4(
                    f2tf(kp[0] * w0), f2tf(kp[KDIM] * w1),
                    f2tf(kp[2 * KDIM] * w2), f2tf(kp[3 * KDIM] * w3));
            }
        }
        __syncthreads();
#pragma unroll
        for (int k8 = 0; k8 < 8; k8++) {
            const int gA = k8 * 2 + a_gsel;
            const int gB = k8 * 2 + b_gsel;
            unsigned af[2][4];
#pragma unroll
            for (int mt = 0; mt < 2; mt++) {
                int r = wm + mt * 16 + a_row;
                ldsm_x4(af[mt], Vt + r * 256 + ((gA ^ (r & 7)) << 4));
            }
            unsigned bfr[4][4];
#pragma unroll
            for (int ntp = 0; ntp < 4; ntp++) {
                int r = wn + ntp * 16 + b_row;
                ldsm_x4(bfr[ntp], Kt + r * 256 + ((gB ^ (r & 7)) << 4));
            }
#pragma unroll
            for (int ntp = 0; ntp < 4; ntp++) {
#pragma unroll
                for (int half = 0; half < 2; half++) {
                    unsigned bf[2] = { bfr[ntp][half * 2], bfr[ntp][half * 2 + 1] };
#pragma unroll
                    for (int mt = 0; mt < 2; mt++)
                        mma_tf32(acc[mt][ntp * 2 + half], af[mt], bf);
                }
            }
        }
        __syncthreads();
    }

    float* St = g_state + (size_t)(bh * NCH + c) * STSZ;
#pragma unroll
    for (int mt = 0; mt < 2; mt++) {
        int r0 = dvt * 128 + wm + mt * 16 + gq;
#pragma unroll
        for (int nt = 0; nt < 8; nt++) {
            int cc = dkt * 128 + wn + nt * 8 + tq * 2;
            *(float2*)(St + (size_t)r0 * DK + cc)       = make_float2(acc[mt][nt][0], acc[mt][nt][1]);
            *(float2*)(St + (size_t)(r0 + 8) * DK + cc) = make_float2(acc[mt][nt][2], acc[mt][nt][3]);
        }
    }
}

// ---------------------------------------------------------------------------
// Phase B: prefix scan; stores tf32-rounded State snapshots (accum fp32).
// ---------------------------------------------------------------------------
__global__ __launch_bounds__(256) void state_scan()
{
    int tid4 = blockIdx.x * 256 + threadIdx.x;
    int bh   = tid4 >> 15;
    int off  = (tid4 & 32767) * 4;
    const float d = expf(head_lam(bh & 3) * (float)CHK);

    float* base = g_state + (size_t)bh * NCH * STSZ + off;
    float4 s = make_float4(0.f, 0.f, 0.f, 0.f);
#pragma unroll
    for (int c = 0; c < NCH; c++) {
        float4 u = *(float4*)(base + (size_t)c * STSZ);
        *(float4*)(base + (size_t)c * STSZ) =
            make_float4(roundtf(s.x), roundtf(s.y), roundtf(s.z), roundtf(s.w));
        s.x = d * s.x + u.x;
        s.y = d * s.y + u.y;
        s.z = d * s.z + u.z;
        s.w = d * s.w + u.w;
    }
}

// ---------------------------------------------------------------------------
// Phase C: O[128,128] = Qhat @ State^T + (mask . Q K^T) @ V, ldmatrix,
// 2 CTAs/SM. Vt transpose uses granule-per-thread (conflict-free).
// ---------------------------------------------------------------------------
constexpr int CO_QS = 0;
constexpr int CO_BS = 16384;
constexpr int CO_SS = 32768;
constexpr int CO_VT = 65536;
constexpr int CO_SMEM = 98304;

__global__ __launch_bounds__(256, 2) void chunk_out()
{
    extern __shared__ char smemc[];
    const uint32_t sb = smem_u32(smemc);
    const uint32_t Qs = sb + CO_QS;
    const uint32_t Bs = sb + CO_BS;
    const uint32_t Ss = sb + CO_SS;
    const uint32_t Vt = sb + CO_VT;

    const int tid  = threadIdx.x;
    const int lane = tid & 31;
    const int wid  = tid >> 5;
    const int gq = lane >> 2;
    const int tq = lane & 3;
    const int wm  = (wid & 3) * 32;
    const int wn  = (wid >> 2) * 64;
    const int wns = (wid >> 2) * 32;

    const int a_row  = (lane & 7) + ((lane >> 3) & 1) * 8;
    const int a_gsel = lane >> 4;
    const int b_row  = (lane & 7) + (lane >> 4) * 8;
    const int b_gsel = (lane >> 3) & 1;

    const int dvt = blockIdx.x;
    const int c   = blockIdx.y;
    const int bh  = blockIdx.z;
    const int b = bh >> 2, h = bh & 3;
    const float lam = head_lam(h);

    const int rowbase = b * T_SEQ + c * CHK;
    const float* Qb = g_q + (size_t)rowbase * KDIM + h * DK;
    const float* Kb = g_k + (size_t)rowbase * KDIM + h * DK;
    const float* Vb = g_v + (size_t)rowbase * VDIM + h * DV + dvt * 128;
    const float* St = g_state + (size_t)(bh * NCH + c) * STSZ + (size_t)dvt * 128 * DK;

    float oacc[2][8][4];
#pragma unroll
    for (int mt = 0; mt < 2; mt++)
#pragma unroll
        for (int nt = 0; nt < 8; nt++)
#pragma unroll
            for (int e = 0; e < 4; e++) oacc[mt][nt][e] = 0.0f;

    // ---------------- cross term: O += Qhat @ State^T ----------------
    for (int kc = 0; kc < DK; kc += 32) {
#pragma unroll
        for (int it = 0; it < 4; it++) {
            int id  = it * 256 + tid;
            int row = id >> 3;
            int g   = id & 7;
            uint32_t off = row * 128 + ((g ^ (row & 7)) << 4);
            float w = expf(lam * (float)row);
            float4 q = *(const float4*)(Qb + (size_t)row * KDIM + kc + g * 4);
            *(uint4*)(smemc + CO_QS + off) =
                make_uint4(f2tf(q.x * w), f2tf(q.y * w), f2tf(q.z * w), f2tf(q.w * w));
            float4 s = *(const float4*)(St + (size_t)row * DK + kc + g * 4);
            *(uint4*)(smemc + CO_BS + off) =
                make_uint4(f2tf(s.x), f2tf(s.y), f2tf(s.z), f2tf(s.w));
        }
        __syncthreads();
#pragma unroll
        for (int k8 = 0; k8 < 4; k8++) {
            const int gA = k8 * 2 + a_gsel;
            const int gB = k8 * 2 + b_gsel;
            unsigned af[2][4];
#pragma unroll
            for (int mt = 0; mt < 2; mt++) {
                int r = wm + mt * 16 + a_row;
                ldsm_x4(af[mt], Qs + r * 128 + ((gA ^ (r & 7)) << 4));
            }
            unsigned bfr[4][4];
#pragma unroll
            for (int ntp = 0; ntp < 4; ntp++) {
                int r = wn + ntp * 16 + b_row;
                ldsm_x4(bfr[ntp], Bs + r * 128 + ((gB ^ (r & 7)) << 4));
            }
#pragma unroll
            for (int ntp = 0; ntp < 4; ntp++) {
#pragma unroll
                for (int half = 0; half < 2; half++) {
                    unsigned bf[2] = { bfr[ntp][half * 2], bfr[ntp][half * 2 + 1] };
#pragma unroll
                    for (int mt = 0; mt < 2; mt++)
                        mma_tf32(oacc[mt][ntp * 2 + half], af[mt], bf);
                }
            }
        }
        __syncthreads();
    }

    // ---------------- intra term, two 64-key halves ----------------
    for (int sh = 0; sh < 2; sh++) {
        float sacc[2][4][4];
#pragma unroll
        for (int mt = 0; mt < 2; mt++)
#pragma unroll
            for (int nt = 0; nt < 4; nt++)
#pragma unroll
                for (int e = 0; e < 4; e++) sacc[mt][nt][e] = 0.0f;

        for (int kc = 0; kc < DK; kc += 32) {
#pragma unroll
            for (int it = 0; it < 4; it++) {
                int id  = it * 256 + tid;
                int row = id >> 3;
                int g   = id & 7;
                uint32_t off = row * 128 + ((g ^ (row & 7)) << 4);
                float4 q = *(const float4*)(Qb + (size_t)row * KDIM + kc + g * 4);
                *(uint4*)(smemc + CO_QS + off) =
                    make_uint4(f2tf(q.x), f2tf(q.y), f2tf(q.z), f2tf(q.w));
            }
#pragma unroll
            for (int it = 0; it < 2; it++) {
                int id  = it * 256 + tid;
                int row = id >> 3;             // 0..63
                int g   = id & 7;
                uint32_t off = row * 128 + ((g ^ (row & 7)) << 4);
                float4 kv = *(const float4*)(Kb + (size_t)(sh * 64 + row) * KDIM + kc + g * 4);
                *(uint4*)(smemc + CO_BS + off) =
                    make_uint4(f2tf(kv.x), f2tf(kv.y), f2tf(kv.z), f2tf(kv.w));
            }
            __syncthreads();
#pragma unroll
            for (int k8 = 0; k8 < 4; k8++) {
                const int gA = k8 * 2 + a_gsel;
                const int gB = k8 * 2 + b_gsel;
                unsigned af[2][4];
#pragma unroll
                for (int mt = 0; mt < 2; mt++) {
                    int r = wm + mt * 16 + a_row;
                    ldsm_x4(af[mt], Qs + r * 128 + ((gA ^ (r & 7)) << 4));
                }
                unsigned bfr[2][4];
#pragma unroll
                for (int ntp = 0; ntp < 2; ntp++) {
                    int r = wns + ntp * 16 + b_row;
                    ldsm_x4(bfr[ntp], Bs + r * 128 + ((gB ^ (r & 7)) << 4));
                }
#pragma unroll
                for (int ntp = 0; ntp < 2; ntp++) {
#pragma unroll
                    for (int half = 0; half < 2; half++) {
                        unsigned bf[2] = { bfr[ntp][half * 2], bfr[ntp][half * 2 + 1] };
#pragma unroll
                        for (int mt = 0; mt < 2; mt++)
                            mma_tf32(sacc[mt][ntp * 2 + half], af[mt], bf);
                    }
                }
            }
            __syncthreads();
        }

        // mask + decay -> Ss (swz256)
#pragma unroll
        for (int mt = 0; mt < 2; mt++) {
#pragma unroll
            for (int nt = 0; nt < 4; nt++) {
#pragma unroll
                for (int e = 0; e < 4; e++) {
                    int r  = wm + mt * 16 + gq + (e >> 1) * 8;
                    int cl = wns + nt * 8 + tq * 2 + (e & 1);
                    int s  = sh * 64 + cl;
                    float w = (r >= s) ? expf(lam * (float)(r - s)) : 0.0f;
                    uint32_t off = r * 256 + (((cl >> 2) ^ (r & 7)) << 4) + (cl & 3) * 4;
                    *(unsigned*)(smemc + CO_SS + off) = f2tf(sacc[mt][nt][e] * w);
                }
            }
        }
        // V^T tile: granule-per-thread transpose (conflict-free STS.128)
#pragma unroll
        for (int g2 = 0; g2 < 2; g2++) {
            int gI = g2 * 8 + (tid >> 5);
            int i0 = sh * 64 + gI * 4;
#pragma unroll
            for (int rr = 0; rr < 4; rr++) {
                int r = rr * 32 + lane;
                uint32_t off = r * 256 + ((gI ^ (r & 7)) << 4);
                const float* vp = Vb + (size_t)i0 * VDIM + r;
                *(uint4*)(smemc + CO_VT + off) = make_uint4(
                    f2tf(vp[0]), f2tf(vp[VDIM]), f2tf(vp[2 * VDIM]), f2tf(vp[3 * VDIM]));
            }
        }
        __syncthreads();

        // O += Ss @ Vt (k = 64)
#pragma unroll
        for (int k8 = 0; k8 < 8; k8++) {
            const int gA = k8 * 2 + a_gsel;
            const int gB = k8 * 2 + b_gsel;
            unsigned af[2][4];
#pragma unroll
            for (int mt = 0; mt < 2; mt++) {
                int r = wm + mt * 16 + a_row;
                ldsm_x4(af[mt], Ss + r * 256 + ((gA ^ (r & 7)) << 4));
            }
            unsigned bfr[4][4];
#pragma unroll
            for (int ntp = 0; ntp < 4; ntp++) {
                int r = wn + ntp * 16 + b_row;
                ldsm_x4(bfr[ntp], Vt + r * 256 + ((gB ^ (r & 7)) << 4));
            }
#pragma unroll
            for (int ntp = 0; ntp < 4; ntp++) {
#pragma unroll
                for (int half = 0; half < 2; half++) {
                    unsigned bf[2] = { bfr[ntp][half * 2], bfr[ntp][half * 2 + 1] };
#pragma unroll
                    for (int mt = 0; mt < 2; mt++)
                        mma_tf32(oacc[mt][ntp * 2 + half], af[mt], bf);
                }
            }
        }
        __syncthreads();
    }

#pragma unroll
    for (int mt = 0; mt < 2; mt++) {
        int r0 = wm + mt * 16 + gq;
#pragma unroll
        for (int nt = 0; nt < 8; nt++) {
            int cc = h * DV + dvt * 128 + wn + nt * 8 + tq * 2;
            size_t row = (size_t)(rowbase + r0);
            *(float2*)(g_o + row * VDIM + cc) =
                make_float2(oacc[mt][nt][0], oacc[mt][nt][1]);
            *(float2*)(g_o + (row + 8) * VDIM + cc) =
                make_float2(oacc[mt][nt][2], oacc[mt][nt][3]);
        }
    }
}

// ---------------------------------------------------------------------------
// RMSNorm * g_norm_w * silu(g); writes tf32-rounded o (feeds out_gemm).
// ---------------------------------------------------------------------------
__global__ __launch_bounds__(256) void gate_kernel(const float* __restrict__ gw)
{
    __shared__ float ws[8];
    const int blk = blockIdx.x;
    const int tid = threadIdx.x;
    const size_t base = (size_t)(blk >> 2) * VDIM + (size_t)(blk & 3) * DV;

    float2 o2 = *(float2*)(g_o + base + tid * 2);
    float p = o2.x * o2.x + o2.y * o2.y;
#pragma unroll
    for (int off = 16; off > 0; off >>= 1) p += __shfl_xor_sync(0xffffffffu, p, off);
    if ((tid & 31) == 0) ws[tid >> 5] = p;
    __syncthreads();
    float tot = ws[0] + ws[1] + ws[2] + ws[3] + ws[4] + ws[5] + ws[6] + ws[7];
    float rms = rsqrtf(tot * (1.0f / (float)DV) + 1e-5f);

    const int c = tid * 2;
    float2 g2 = *(const float2*)(g_g + base + c);
    float s0 = g2.x / (1.0f + expf(-g2.x));
    float s1 = g2.y / (1.0f + expf(-g2.y));
    o2.x = roundtf(o2.x * rms * gw[c] * s0);
    o2.y = roundtf(o2.y * rms * gw[c + 1] * s1);
    *(float2*)(g_o + base + c) = o2;
}

// ---------------------------------------------------------------------------
extern "C" void kernel_launch(void* const* d_in, const int* in_sizes, int n_in,
                              void* d_out, int out_size)
{
    const float* x  = (const float*)d_in[0];
    const float* Wq = (const float*)d_in[1];
    const float* Wk = (const float*)d_in[2];
    const float* Wv = (const float*)d_in[3];
    const float* Wg = (const float*)d_in[4];
    const float* Wo = (const float*)d_in[5];
    const float* gw = (const float*)d_in[6];
    float* out = (float*)d_out;

    cudaFuncSetAttribute(proj_gemm, cudaFuncAttributeMaxDynamicSharedMemorySize, GEMM_SMEM);
    cudaFuncSetAttribute(out_gemm,  cudaFuncAttributeMaxDynamicSharedMemorySize, GEMM_SMEM);
    cudaFuncSetAttribute(chunk_kv,  cudaFuncAttributeMaxDynamicSharedMemorySize, KV_SMEM);
    cudaFuncSetAttribute(chunk_out, cudaFuncAttributeMaxDynamicSharedMemorySize, CO_SMEM);

    // Pre-round all inputs to tf32 in one launch
    round_all<<<12288, 256>>>(x, Wq, Wk, Wv, Wg, Wo);

    // Fused projections
    dim3 gp(48, 32);
    proj_gemm<<<gp, 256, GEMM_SMEM>>>();

    rope_kernel<<<(NB * T_SEQ * NH * 128) / 256, 256>>>();

    dim3 ga(8, NCH, NB * NH);
    chunk_kv<<<ga, 256, KV_SMEM>>>();

    state_scan<<<1024, 256>>>();

    dim3 gc(4, NCH, NB * NH);
    chunk_out<<<gc, 256, CO_SMEM>>>();

    gate_kernel<<<MROWS * NH, 256>>>(gw);

    dim3 go(8, 32);
    out_gemm<<<go, 256, GEMM_SMEM>>>(out);
}